// round 6
// baseline (speedup 1.0000x reference)
#include <cuda_runtime.h>

#define B_ 256
#define S_ 512
#define V_ 32000
#define D_ 100
#define H_ 75
#define HP_ 76   // g_embp row stride
#define KP_ 80   // padded k dimension (4 chunks of 20)
#define L_ 128

// Precomputed emb @ W1^T + b1, stride 76. 32000*76*4 = 9.73 MB (L2-resident).
__device__ float g_embp[V_ * HP_];

// ---------------------------------------------------------------------------
// Kernel 1: embp[v][j] = sum_d emb[v][d] * W1[j][d] + b1[j]
// ---------------------------------------------------------------------------
__global__ __launch_bounds__(256) void embp_kernel(const float* __restrict__ emb,
                                                   const float* __restrict__ W1,
                                                   const float* __restrict__ b1) {
    __shared__ float w1s[H_ * D_];
    __shared__ float es[64 * D_];
    const int r0 = blockIdx.x * 64;

    for (int idx = threadIdx.x; idx < H_ * D_; idx += 256) w1s[idx] = W1[idx];
    for (int idx = threadIdx.x; idx < 64 * D_; idx += 256) es[idx] = emb[r0 * D_ + idx];
    __syncthreads();

    for (int o = threadIdx.x; o < 64 * H_; o += 256) {
        const int rr = o / H_;
        const int j  = o - rr * H_;
        const float* ep = es + rr * D_;
        const float* wp = w1s + j * D_;
        float4 a = {0.f, 0.f, 0.f, 0.f};
#pragma unroll
        for (int k = 0; k < D_ / 4; ++k) {
            float4 ev = *(const float4*)(ep + 4 * k);
            float4 wv = *(const float4*)(wp + 4 * k);
            a.x += ev.x * wv.x; a.y += ev.y * wv.y;
            a.z += ev.z * wv.z; a.w += ev.w * wv.w;
        }
        g_embp[(r0 + rr) * HP_ + j] = a.x + a.y + a.z + a.w + b1[j];
    }
}

// ---------------------------------------------------------------------------
// Packed fp32x2 helpers (sm_103a)
// ---------------------------------------------------------------------------
__device__ __forceinline__ unsigned long long pack2(float lo, float hi) {
    unsigned long long d;
    asm("mov.b64 %0, {%1, %2};" : "=l"(d) : "f"(lo), "f"(hi));
    return d;
}
__device__ __forceinline__ void fma2(unsigned long long& d, unsigned long long a,
                                     unsigned long long b) {
    asm("fma.rn.f32x2 %0, %1, %2, %0;" : "+l"(d) : "l"(a), "l"(b));
}
__device__ __forceinline__ float hsum2(unsigned long long a, unsigned long long b) {
    unsigned long long s;
    asm("add.rn.f32x2 %0, %1, %2;" : "=l"(s) : "l"(a), "l"(b));
    float lo, hi;
    asm("mov.b64 {%0, %1}, %2;" : "=f"(lo), "=f"(hi) : "l"(s));
    return lo + hi;
}
__device__ __forceinline__ float sigm(float z) { return 1.f / (1.f + __expf(-z)); }
__device__ __forceinline__ float bfly4(float v) {
    v += __shfl_xor_sync(0xffffffffu, v, 1);
    v += __shfl_xor_sync(0xffffffffu, v, 2);
    return v;
}

// ---------------------------------------------------------------------------
// Kernel 2: persistent-weight recurrence. 128 blocks x 512 threads, 2 rows/block.
// Quad of adjacent lanes owns the 4 k-chunks of each output; shfl_xor butterfly
// reduction; double-buffered h/o state; ONE __syncthreads per step.
// Pipeline at step tt: A(tt) h-update, B(tt-1) o, C(tt-2) fc output.
// ---------------------------------------------------------------------------
__global__ __launch_bounds__(512, 1) void rnn_kernel(
    const int*   __restrict__ X,
    const float* __restrict__ W2, const float* __restrict__ b2,
    const float* __restrict__ Wo, const float* __restrict__ bo,
    const float* __restrict__ Wfc, const float* __restrict__ bfc,
    float* __restrict__ out)
{
    __shared__ __align__(16) float hs[2][2][KP_];   // [buf][row][k]
    __shared__ __align__(16) float os[2][2][KP_];
    __shared__ int toks[2][S_];

    const int tid = threadIdx.x;
    const int b0  = blockIdx.x * 2;

    const int grp = tid >> 2;          // output index within role
    const int q   = tid & 3;           // k-chunk 0..3
    const int k0  = q * 20;
    const bool abWarp = tid < 320;     // warps 0..9 run the AB path (uniform per warp)
    const bool abj    = grp < H_;      // valid j for AB (tid < 300)
    const int j = grp;                 // AB output (0..74 when abj)
    const int l = grp;                 // C output (0..127)

    // ---- init state + tokens ----
    for (int idx = tid; idx < 2 * 2 * KP_; idx += 512) {
        ((float*)hs)[idx] = 0.f; ((float*)os)[idx] = 0.f;
    }
    for (int idx = tid; idx < 2 * S_; idx += 512) {
        const int i = idx >> 9, t = idx & (S_ - 1);
        toks[i][t] = X[(b0 + i) * S_ + t];
    }

    // ---- weights into registers (packed k-pairs) ----
    unsigned long long w2p[10], wop[10], wfp[10];
#pragma unroll
    for (int c = 0; c < 10; ++c) {
        const int k = k0 + 2 * c;
        float lo = 0.f, hi = 0.f;
        if (abj) {
            if (k     < H_) lo = W2[j * H_ + k];
            if (k + 1 < H_) hi = W2[j * H_ + k + 1];
        }
        w2p[c] = pack2(lo, hi);
        lo = 0.f; hi = 0.f;
        if (abj) {
            if (k     < H_) lo = Wo[j * H_ + k];
            if (k + 1 < H_) hi = Wo[j * H_ + k + 1];
        }
        wop[c] = pack2(lo, hi);
        lo = 0.f; hi = 0.f;
        if (k     < H_) lo = Wfc[l * H_ + k];
        if (k + 1 < H_) hi = Wfc[l * H_ + k + 1];
        wfp[c] = pack2(lo, hi);
    }

    float b2r = 0.f, bor = 0.f;
    if (abj) { b2r = b2[j]; bor = bo[j]; }
    const float bfcr = bfc[l];
    // C store: lane q==0 writes row 0, q==1 writes row 1
    float* outp = out + ((size_t)(b0 + (q & 1)) * S_) * L_ + l;

    __syncthreads();

    // xp prefetch (lane q==0 of each AB quad holds xp for both rows)
    float xp0 = 0.f, xp1 = 0.f;
    if (abj && q == 0) {
        xp0 = g_embp[(size_t)toks[0][0] * HP_ + j];
        xp1 = g_embp[(size_t)toks[1][0] * HP_ + j];
    }

    for (int tt = 0; tt < S_ + 2; ++tt) {
        const int pb  = tt & 1;
        const int pb1 = pb ^ 1;

        // ---- C partials: fc of o_{tt-2} (read os[pb1]) ----
        float c0 = 0.f, c1 = 0.f;
        if (tt >= 2) {
#pragma unroll
            for (int i = 0; i < 2; ++i) {
                const ulonglong2* op = (const ulonglong2*)&os[pb1][i][k0];
                unsigned long long a0 = 0ull, a1 = 0ull;
#pragma unroll
                for (int c = 0; c < 5; ++c) {
                    const ulonglong2 ov = op[c];          // broadcast LDS.128
                    fma2(a0, wfp[2 * c],     ov.x);
                    fma2(a1, wfp[2 * c + 1], ov.y);
                }
                if (i == 0) c0 = hsum2(a0, a1); else c1 = hsum2(a0, a1);
            }
            c0 = bfly4(c0);
            c1 = bfly4(c1);
        }

        // ---- A/B partials: read h_{tt-1} = hs[pb] ----
        float zA0 = 0.f, zA1 = 0.f, zB0 = 0.f, zB1 = 0.f;
        if (abWarp && tt <= S_) {
#pragma unroll
            for (int i = 0; i < 2; ++i) {
                const ulonglong2* hp = (const ulonglong2*)&hs[pb][i][k0];
                unsigned long long a0 = 0ull, a1 = 0ull, d0 = 0ull, d1 = 0ull;
#pragma unroll
                for (int c = 0; c < 5; ++c) {
                    const ulonglong2 hv = hp[c];          // broadcast LDS.128
                    fma2(a0, w2p[2 * c],     hv.x);
                    fma2(d0, wop[2 * c],     hv.x);
                    fma2(a1, w2p[2 * c + 1], hv.y);
                    fma2(d1, wop[2 * c + 1], hv.y);
                }
                if (i == 0) { zA0 = hsum2(a0, a1); zB0 = hsum2(d0, d1); }
                else        { zA1 = hsum2(a0, a1); zB1 = hsum2(d0, d1); }
            }
            zA0 = bfly4(zA0); zB0 = bfly4(zB0);
            zA1 = bfly4(zA1); zB1 = bfly4(zB1);
        }

        // ---- finalize ----
        if (abj) {
            if (q == 0 && tt < S_) {                       // h_tt -> hs[pb1]
                hs[pb1][0][j] = sigm(zA0 + xp0 + b2r);
                hs[pb1][1][j] = sigm(zA1 + xp1 + b2r);
                if (tt + 1 < S_) {
                    xp0 = g_embp[(size_t)toks[0][tt + 1] * HP_ + j];
                    xp1 = g_embp[(size_t)toks[1][tt + 1] * HP_ + j];
                }
            }
            if (q == 1 && tt >= 1 && tt <= S_) {           // o_{tt-1} -> os[pb]
                os[pb][0][j] = sigm(zB0 + bor);
                os[pb][1][j] = sigm(zB1 + bor);
            }
        }
        if (tt >= 2 && q < 2) {                            // out_{tt-2}
            const float v = (q == 0 ? c0 : c1) + bfcr;
            outp[(size_t)(tt - 2) * L_] = v;
        }

        __syncthreads();   // state writes (other buffer) visible for next step
    }
}

// ---------------------------------------------------------------------------
extern "C" void kernel_launch(void* const* d_in, const int* in_sizes, int n_in,
                              void* d_out, int out_size) {
    const int*   X   = (const int*)d_in[0];
    const float* emb = (const float*)d_in[1];
    const float* W1  = (const float*)d_in[2];
    const float* b1  = (const float*)d_in[3];
    const float* W2  = (const float*)d_in[4];
    const float* b2  = (const float*)d_in[5];
    const float* Wo  = (const float*)d_in[6];
    const float* bo  = (const float*)d_in[7];
    const float* Wfc = (const float*)d_in[8];
    const float* bfc = (const float*)d_in[9];
    float* out = (float*)d_out;

    embp_kernel<<<V_ / 64, 256>>>(emb, W1, b1);
    rnn_kernel<<<B_ / 2, 512>>>(X, W2, b2, Wo, bo, Wfc, bfc, out);
}

// round 8
// speedup vs baseline: 1.4174x; 1.4174x over previous
#include <cuda_runtime.h>

#define B_ 256
#define S_ 512
#define V_ 32000
#define D_ 100
#define H_ 75
#define HP_ 76   // g_embp row stride
#define KP_ 80   // padded k dimension (4 chunks of 20)
#define L_ 128

// Precomputed emb @ W1^T + b1, stride 76. 32000*76*4 = 9.73 MB (L2-resident).
__device__ float g_embp[V_ * HP_];

// ---------------------------------------------------------------------------
// Kernel 1: embp[v][j] = sum_d emb[v][d] * W1[j][d] + b1[j]
// ---------------------------------------------------------------------------
__global__ __launch_bounds__(256) void embp_kernel(const float* __restrict__ emb,
                                                   const float* __restrict__ W1,
                                                   const float* __restrict__ b1) {
    __shared__ float w1s[H_ * D_];
    __shared__ float es[64 * D_];
    const int r0 = blockIdx.x * 64;

    for (int idx = threadIdx.x; idx < H_ * D_; idx += 256) w1s[idx] = W1[idx];
    for (int idx = threadIdx.x; idx < 64 * D_; idx += 256) es[idx] = emb[r0 * D_ + idx];
    __syncthreads();

    for (int o = threadIdx.x; o < 64 * H_; o += 256) {
        const int rr = o / H_;
        const int j  = o - rr * H_;
        const float* ep = es + rr * D_;
        const float* wp = w1s + j * D_;
        float4 a = {0.f, 0.f, 0.f, 0.f};
#pragma unroll
        for (int k = 0; k < D_ / 4; ++k) {
            float4 ev = *(const float4*)(ep + 4 * k);
            float4 wv = *(const float4*)(wp + 4 * k);
            a.x += ev.x * wv.x; a.y += ev.y * wv.y;
            a.z += ev.z * wv.z; a.w += ev.w * wv.w;
        }
        g_embp[(r0 + rr) * HP_ + j] = a.x + a.y + a.z + a.w + b1[j];
    }
}

// ---------------------------------------------------------------------------
// Packed fp32x2 helpers (sm_103a)
// ---------------------------------------------------------------------------
__device__ __forceinline__ unsigned long long pack2(float lo, float hi) {
    unsigned long long d;
    asm("mov.b64 %0, {%1, %2};" : "=l"(d) : "f"(lo), "f"(hi));
    return d;
}
__device__ __forceinline__ void fma2(unsigned long long& d, unsigned long long a,
                                     unsigned long long b) {
    asm("fma.rn.f32x2 %0, %1, %2, %0;" : "+l"(d) : "l"(a), "l"(b));
}
__device__ __forceinline__ float hsum2(unsigned long long a, unsigned long long b) {
    unsigned long long s;
    asm("add.rn.f32x2 %0, %1, %2;" : "=l"(s) : "l"(a), "l"(b));
    float lo, hi;
    asm("mov.b64 {%0, %1}, %2;" : "=f"(lo), "=f"(hi) : "l"(s));
    return lo + hi;
}

// ---------------------------------------------------------------------------
// MUFU-free sigmoid.  e = 2^(-|z|*log2e) via magic-round + deg-6 poly +
// exponent bit-build; r = 1/(1+e) via Chebyshev quadratic seed on [1,2]
// (max rel err 0.86%) + 2 Newton steps (-> ~5e-9). All FMA/ALU pipe.
// Verified: sigm(0)=0.5, sigm(1)=0.731058 (true 0.7310586).
// ---------------------------------------------------------------------------
__device__ __forceinline__ float sigm(float z) {
    const float zc = fminf(fmaxf(z, -30.f), 30.f);
    const float az = fabsf(zc);
    const float t  = az * -1.44269504088896341f;     // -|z|*log2(e), in [-43.3, 0]
    const float rn = t + 12582912.0f;                // 1.5 * 2^23 magic round
    const float n  = rn - 12582912.0f;
    const float f  = t - n;                          // f in [-0.5, 0.5]
    // 2^f via degree-6 Taylor of e^{f ln2} (trunc err < 1.2e-7)
    float p = 1.54035304e-4f;
    p = fmaf(p, f, 1.33335581e-3f);
    p = fmaf(p, f, 9.61812911e-3f);
    p = fmaf(p, f, 5.55041087e-2f);
    p = fmaf(p, f, 2.40226507e-1f);
    p = fmaf(p, f, 6.93147181e-1f);
    p = fmaf(p, f, 1.0f);
    // scale = 2^n via exponent bits (n in [-44, 0])
    const int ni = __float_as_int(rn) - 0x4B400000;  // integer n
    const float scale = __int_as_float((127 + ni) << 23);
    const float e = p * scale;                       // e^{-|z|} in (9e-14, 1]
    // r = 1/(1+e), d in (1, 2]
    const float d = 1.0f + e;
    float r = fmaf(d, fmaf(d, 0.333048f, -1.484426f), 2.142761f);  // Chebyshev seed
    r = fmaf(-d, r, 2.0f) * r;   // Newton 1
    r = r * fmaf(-d, r, 2.0f);   // Newton 2
    // sigma(z) = z>=0 ? 1/(1+e) : e/(1+e)
    return (z >= 0.f) ? r : e * r;
}

// ---------------------------------------------------------------------------
// Kernel 2 (R5 structure): persistent-weight recurrence. 128 blocks x 512
// threads, 2 rows/block. Register-resident packed-f32x2 weights. Pipeline at
// step tt: A(tt) h-update, B(tt-1) o, C(tt-2) fc. 2 barriers/step.
// ---------------------------------------------------------------------------
__global__ __launch_bounds__(512, 1) void rnn_kernel(
    const int*   __restrict__ X,
    const float* __restrict__ W2, const float* __restrict__ b2,
    const float* __restrict__ Wo, const float* __restrict__ bo,
    const float* __restrict__ Wfc, const float* __restrict__ bfc,
    float* __restrict__ out)
{
    __shared__ __align__(16) float hs[2][KP_];
    __shared__ __align__(16) float os[2][KP_];
    __shared__ float pA[2][4][KP_];
    __shared__ float pB[2][4][KP_];
    __shared__ float pC[2][4][L_];
    __shared__ int   toks[2][S_];

    const int tid = threadIdx.x;
    const int b0  = blockIdx.x * 2;

    const bool isAB = tid < 4 * H_;
    const int  ja   = tid % H_;
    const int  qa   = tid / H_;
    const int  ka0  = (isAB ? qa : 0) * 20;
    const int  lc   = tid & 127;
    const int  qc   = tid >> 7;
    const int  kc0  = qc * 20;
    const bool isR  = tid < 256;
    const int  ir   = tid >> 7;
    const int  rr   = tid & 127;

    for (int idx = tid; idx < 2 * KP_; idx += 512) {
        ((float*)hs)[idx] = 0.f; ((float*)os)[idx] = 0.f;
    }
    for (int idx = tid; idx < 2 * S_; idx += 512) {
        const int i = idx >> 9, t = idx & (S_ - 1);
        toks[i][t] = X[(b0 + i) * S_ + t];
    }

    unsigned long long w2p[10], wop[10], wfp[10];
#pragma unroll
    for (int c = 0; c < 10; ++c) {
        const int k = ka0 + 2 * c;
        float lo = 0.f, hi = 0.f;
        if (isAB) {
            if (k     < H_) lo = W2[ja * H_ + k];
            if (k + 1 < H_) hi = W2[ja * H_ + k + 1];
        }
        w2p[c] = pack2(lo, hi);
        lo = 0.f; hi = 0.f;
        if (isAB) {
            if (k     < H_) lo = Wo[ja * H_ + k];
            if (k + 1 < H_) hi = Wo[ja * H_ + k + 1];
        }
        wop[c] = pack2(lo, hi);
        const int kc = kc0 + 2 * c;
        lo = 0.f; hi = 0.f;
        if (kc     < H_) lo = Wfc[lc * H_ + kc];
        if (kc + 1 < H_) hi = Wfc[lc * H_ + kc + 1];
        wfp[c] = pack2(lo, hi);
    }

    float b2r = 0.f, bor = 0.f, bfcr = 0.f;
    if (isR) {
        if (rr < H_) { b2r = b2[rr]; bor = bo[rr]; }
        bfcr = bfc[rr];
    }
    float* outp = out + ((size_t)(b0 + ir) * S_) * L_ + rr;

    __syncthreads();

    float xpv = 0.f;
    if (isR && rr < H_) xpv = g_embp[(size_t)toks[ir][0] * HP_ + rr];

    for (int tt = 0; tt < S_ + 2; ++tt) {
        const bool doA = tt < S_;
        const bool doB = (tt >= 1) && (tt <= S_);
        const bool doC = tt >= 2;

        // --- partial phase ---
        if (doC) {
#pragma unroll
            for (int i = 0; i < 2; ++i) {
                const ulonglong2* op = (const ulonglong2*)&os[i][kc0];
                unsigned long long a0 = 0ull, a1 = 0ull;
#pragma unroll
                for (int c = 0; c < 5; ++c) {
                    const ulonglong2 ov = op[c];      // broadcast LDS.128
                    fma2(a0, wfp[2 * c],     ov.x);
                    fma2(a1, wfp[2 * c + 1], ov.y);
                }
                pC[i][qc][lc] = hsum2(a0, a1);
            }
        }
        if (isAB && (doA || doB)) {
#pragma unroll
            for (int i = 0; i < 2; ++i) {
                const ulonglong2* hp = (const ulonglong2*)&hs[i][ka0];
                unsigned long long a0 = 0ull, a1 = 0ull, c0 = 0ull, c1 = 0ull;
#pragma unroll
                for (int c = 0; c < 5; ++c) {
                    const ulonglong2 hv = hp[c];      // broadcast LDS.128, shared by A & B
                    fma2(a0, w2p[2 * c],     hv.x);
                    fma2(c0, wop[2 * c],     hv.x);
                    fma2(a1, w2p[2 * c + 1], hv.y);
                    fma2(c1, wop[2 * c + 1], hv.y);
                }
                pA[i][qa][ja] = hsum2(a0, a1);
                pB[i][qa][ja] = hsum2(c0, c1);
            }
        }
        __syncthreads();

        // --- reduce phase ---
        if (isR) {
            if (doB && rr < H_) {
                const float z = pB[ir][0][rr] + pB[ir][1][rr]
                              + pB[ir][2][rr] + pB[ir][3][rr] + bor;
                os[ir][rr] = sigm(z);                 // o_{tt-1}
            }
            if (doA && rr < H_) {
                const float z = pA[ir][0][rr] + pA[ir][1][rr]
                              + pA[ir][2][rr] + pA[ir][3][rr] + xpv + b2r;
                hs[ir][rr] = sigm(z);                 // h_tt
                if (tt + 1 < S_)
                    xpv = g_embp[(size_t)toks[ir][tt + 1] * HP_ + rr];
            }
            if (doC) {
                const float v = pC[ir][0][rr] + pC[ir][1][rr]
                              + pC[ir][2][rr] + pC[ir][3][rr] + bfcr;
                outp[(size_t)(tt - 2) * L_] = v;      // out_{tt-2}
            }
        }
        __syncthreads();
    }
}

// ---------------------------------------------------------------------------
extern "C" void kernel_launch(void* const* d_in, const int* in_sizes, int n_in,
                              void* d_out, int out_size) {
    const int*   X   = (const int*)d_in[0];
    const float* emb = (const float*)d_in[1];
    const float* W1  = (const float*)d_in[2];
    const float* b1  = (const float*)d_in[3];
    const float* W2  = (const float*)d_in[4];
    const float* b2  = (const float*)d_in[5];
    const float* Wo  = (const float*)d_in[6];
    const float* bo  = (const float*)d_in[7];
    const float* Wfc = (const float*)d_in[8];
    const float* bfc = (const float*)d_in[9];
    float* out = (float*)d_out;

    embp_kernel<<<V_ / 64, 256>>>(emb, W1, b1);
    rnn_kernel<<<B_ / 2, 512>>>(X, W2, b2, Wo, bo, Wfc, bfc, out);
}

// round 9
// speedup vs baseline: 1.6900x; 1.1923x over previous
#include <cuda_runtime.h>

#define B_ 256
#define S_ 512
#define V_ 32000
#define D_ 100
#define H_ 75
#define HP_ 76   // g_embp row stride
#define KP_ 80   // padded state stride (76 used, 16B-aligned rows)
#define L_ 128
#define NTHR 576 // 18 warps: A=0..4, B=5..9, C=10..17

// Precomputed emb @ W1^T + b1, stride 76. 32000*76*4 = 9.73 MB (L2-resident).
__device__ float g_embp[V_ * HP_];

// ---------------------------------------------------------------------------
// Kernel 1: embp[v][j] = sum_d emb[v][d] * W1[j][d] + b1[j]
// ---------------------------------------------------------------------------
__global__ __launch_bounds__(256) void embp_kernel(const float* __restrict__ emb,
                                                   const float* __restrict__ W1,
                                                   const float* __restrict__ b1) {
    __shared__ float w1s[H_ * D_];
    __shared__ float es[64 * D_];
    const int r0 = blockIdx.x * 64;

    for (int idx = threadIdx.x; idx < H_ * D_; idx += 256) w1s[idx] = W1[idx];
    for (int idx = threadIdx.x; idx < 64 * D_; idx += 256) es[idx] = emb[r0 * D_ + idx];
    __syncthreads();

    for (int o = threadIdx.x; o < 64 * H_; o += 256) {
        const int rr = o / H_;
        const int j  = o - rr * H_;
        const float* ep = es + rr * D_;
        const float* wp = w1s + j * D_;
        float4 a = {0.f, 0.f, 0.f, 0.f};
#pragma unroll
        for (int k = 0; k < D_ / 4; ++k) {
            float4 ev = *(const float4*)(ep + 4 * k);
            float4 wv = *(const float4*)(wp + 4 * k);
            a.x += ev.x * wv.x; a.y += ev.y * wv.y;
            a.z += ev.z * wv.z; a.w += ev.w * wv.w;
        }
        g_embp[(r0 + rr) * HP_ + j] = a.x + a.y + a.z + a.w + b1[j];
    }
}

// ---------------------------------------------------------------------------
// Packed fp32x2 helpers (sm_103a)
// ---------------------------------------------------------------------------
__device__ __forceinline__ unsigned long long pack2(float lo, float hi) {
    unsigned long long d;
    asm("mov.b64 %0, {%1, %2};" : "=l"(d) : "f"(lo), "f"(hi));
    return d;
}
__device__ __forceinline__ void fma2(unsigned long long& d, unsigned long long a,
                                     unsigned long long b) {
    asm("fma.rn.f32x2 %0, %1, %2, %0;" : "+l"(d) : "l"(a), "l"(b));
}
__device__ __forceinline__ float hsum4(unsigned long long a, unsigned long long b,
                                       unsigned long long c, unsigned long long d) {
    unsigned long long s0, s1;
    asm("add.rn.f32x2 %0, %1, %2;" : "=l"(s0) : "l"(a), "l"(b));
    asm("add.rn.f32x2 %0, %1, %2;" : "=l"(s1) : "l"(c), "l"(d));
    asm("add.rn.f32x2 %0, %1, %2;" : "=l"(s0) : "l"(s0), "l"(s1));
    float lo, hi;
    asm("mov.b64 {%0, %1}, %2;" : "=f"(lo), "=f"(hi) : "l"(s0));
    return lo + hi;
}
__device__ __forceinline__ float sigm(float z) {
    return __fdividef(1.0f, 1.0f + __expf(-z));
}

// Full 76-float dot of smem vector (16B-aligned, padded with zeros) against
// 38 packed-f32x2 register weights. 4 accumulators -> dep chain depth ~10.
__device__ __forceinline__ float dot76(const float* __restrict__ v,
                                       const unsigned long long* __restrict__ w) {
    const ulonglong2* p = (const ulonglong2*)v;
    unsigned long long a0 = 0ull, a1 = 0ull, a2 = 0ull, a3 = 0ull;
#pragma unroll
    for (int i = 0; i < 19; ++i) {
        const ulonglong2 hv = p[i];               // broadcast LDS.128
        if (i & 1) { fma2(a2, w[2 * i], hv.x); fma2(a3, w[2 * i + 1], hv.y); }
        else       { fma2(a0, w[2 * i], hv.x); fma2(a1, w[2 * i + 1], hv.y); }
    }
    return hsum4(a0, a1, a2, a3);
}

// ---------------------------------------------------------------------------
// Kernel 2: persistent-weight recurrence, NO cross-thread reduction.
// 128 blocks x 576 threads; block owns 2 batch rows.
//   warps 0-4  (150 lanes): A  h_tt     = sigm(W2 . h_{tt-1} + xp_tt + b2)
//   warps 5-9  (150 lanes): B  o_{tt-1} = sigm(Wo . h_{tt-1} + bo)
//   warps 10-17(256 lanes): C  out_{tt-2} = Wfc . o_{tt-2} + bfc
// Each thread owns one full output row dot (38 packed f32x2 weight regs).
// Double-buffered h/o state; ONE __syncthreads per step.
// ---------------------------------------------------------------------------
__global__ __launch_bounds__(NTHR, 1) void rnn_kernel(
    const int*   __restrict__ X,
    const float* __restrict__ W2, const float* __restrict__ b2,
    const float* __restrict__ Wo, const float* __restrict__ bo,
    const float* __restrict__ Wfc, const float* __restrict__ bfc,
    float* __restrict__ out)
{
    __shared__ __align__(16) float hs[2][2][KP_];   // [buf][row][k]
    __shared__ __align__(16) float os[2][2][KP_];
    __shared__ int toks[2][S_];

    const int tid = threadIdx.x;
    const int wid = tid >> 5;
    const int b0  = blockIdx.x * 2;

    const bool isA = wid < 5;
    const bool isB = (wid >= 5) && (wid < 10);
    // role-local index
    int idx  = isA ? tid : (isB ? tid - 160 : tid - 320);
    bool valid = isA || isB ? (idx < 2 * H_) : true;
    if (!valid) idx = 0;
    int r, j;
    if (isA || isB) { r = (idx >= H_) ? 1 : 0; j = idx - r * H_; }
    else            { r = idx >> 7;            j = idx & 127; }

    // ---- init state + tokens ----
    for (int i = tid; i < 2 * 2 * KP_; i += NTHR) {
        ((float*)hs)[i] = 0.f; ((float*)os)[i] = 0.f;
    }
    for (int i = tid; i < 2 * S_; i += NTHR) {
        const int rr = i >> 9, t = i & (S_ - 1);
        toks[rr][t] = X[(b0 + rr) * S_ + t];
    }

    // ---- weights: one row per thread, packed k-pairs (38 x u64) ----
    const float* wrow = isA ? (W2 + j * H_) : (isB ? (Wo + j * H_) : (Wfc + j * H_));
    unsigned long long w[38];
#pragma unroll
    for (int c = 0; c < 38; ++c) {
        const int k = 2 * c;
        float lo = 0.f, hi = 0.f;
        if (valid) {
            if (k     < H_) lo = wrow[k];
            if (k + 1 < H_) hi = wrow[k + 1];
        }
        w[c] = pack2(lo, hi);
    }
    float br = 0.f;
    if (valid) br = isA ? b2[j] : (isB ? bo[j] : bfc[j]);
    float* outp = out + ((size_t)(b0 + r) * S_) * L_ + j;   // used by C

    __syncthreads();

    float xpv = 0.f;
    if (isA && valid) xpv = g_embp[(size_t)toks[r][0] * HP_ + j];

    for (int tt = 0; tt < S_ + 2; ++tt) {
        const int pb = tt & 1;
        const bool act = valid &&
            (isA ? (tt < S_) : (isB ? (tt >= 1 && tt <= S_) : (tt >= 2)));

        if (act) {
            if (isA) {
                float xn = 0.f;
                if (tt + 1 < S_)                         // prefetch next xp (LDG overlaps dot)
                    xn = g_embp[(size_t)toks[r][tt + 1] * HP_ + j];
                const float z = dot76(hs[pb][r], w) + xpv + br;
                hs[pb ^ 1][r][j] = sigm(z);              // h_tt
                xpv = xn;
            } else if (isB) {
                const float z = dot76(hs[pb][r], w) + br;
                os[pb][r][j] = sigm(z);                  // o_{tt-1}
            } else {
                const float z = dot76(os[pb ^ 1][r], w) + br;
                outp[(size_t)(tt - 2) * L_] = z;         // out_{tt-2}
            }
        }
        __syncthreads();   // all buffer writes visible; no read/write overlap within a step
    }
}

// ---------------------------------------------------------------------------
extern "C" void kernel_launch(void* const* d_in, const int* in_sizes, int n_in,
                              void* d_out, int out_size) {
    const int*   X   = (const int*)d_in[0];
    const float* emb = (const float*)d_in[1];
    const float* W1  = (const float*)d_in[2];
    const float* b1  = (const float*)d_in[3];
    const float* W2  = (const float*)d_in[4];
    const float* b2  = (const float*)d_in[5];
    const float* Wo  = (const float*)d_in[6];
    const float* bo  = (const float*)d_in[7];
    const float* Wfc = (const float*)d_in[8];
    const float* bfc = (const float*)d_in[9];
    float* out = (float*)d_out;

    embp_kernel<<<V_ / 64, 256>>>(emb, W1, b1);
    rnn_kernel<<<B_ / 2, NTHR>>>(X, W2, b2, Wo, bo, Wfc, bfc, out);
}

// round 11
// speedup vs baseline: 2.0631x; 1.2208x over previous
#include <cuda_runtime.h>

#define B_ 256
#define S_ 512
#define V_ 32000
#define D_ 100
#define H_ 75
#define HP_ 76   // g_embp row stride
#define KP_ 80   // padded state stride (76 used, 16B-aligned)
#define L_ 128
#define NTHR 320 // 10 warps: A=0..2, B=3..5, C=6..9  (one batch row per block)

// Precomputed emb @ W1^T + b1, stride 76. 32000*76*4 = 9.73 MB (L2-resident).
__device__ float g_embp[V_ * HP_];

// ---------------------------------------------------------------------------
// Kernel 1: embp[v][j] = sum_d emb[v][d] * W1[j][d] + b1[j]
// ---------------------------------------------------------------------------
__global__ __launch_bounds__(256) void embp_kernel(const float* __restrict__ emb,
                                                   const float* __restrict__ W1,
                                                   const float* __restrict__ b1) {
    __shared__ float w1s[H_ * D_];
    __shared__ float es[64 * D_];
    const int r0 = blockIdx.x * 64;

    for (int idx = threadIdx.x; idx < H_ * D_; idx += 256) w1s[idx] = W1[idx];
    for (int idx = threadIdx.x; idx < 64 * D_; idx += 256) es[idx] = emb[r0 * D_ + idx];
    __syncthreads();

    for (int o = threadIdx.x; o < 64 * H_; o += 256) {
        const int rr = o / H_;
        const int j  = o - rr * H_;
        const float* ep = es + rr * D_;
        const float* wp = w1s + j * D_;
        float4 a = {0.f, 0.f, 0.f, 0.f};
#pragma unroll
        for (int k = 0; k < D_ / 4; ++k) {
            float4 ev = *(const float4*)(ep + 4 * k);
            float4 wv = *(const float4*)(wp + 4 * k);
            a.x += ev.x * wv.x; a.y += ev.y * wv.y;
            a.z += ev.z * wv.z; a.w += ev.w * wv.w;
        }
        g_embp[(r0 + rr) * HP_ + j] = a.x + a.y + a.z + a.w + b1[j];
    }
}

// ---------------------------------------------------------------------------
// Packed fp32x2 helpers (sm_103a)
// ---------------------------------------------------------------------------
__device__ __forceinline__ unsigned long long pack2(float lo, float hi) {
    unsigned long long d;
    asm("mov.b64 %0, {%1, %2};" : "=l"(d) : "f"(lo), "f"(hi));
    return d;
}
__device__ __forceinline__ void fma2(unsigned long long& d, unsigned long long a,
                                     unsigned long long b) {
    asm("fma.rn.f32x2 %0, %1, %2, %0;" : "+l"(d) : "l"(a), "l"(b));
}
__device__ __forceinline__ float hsum4(unsigned long long a, unsigned long long b,
                                       unsigned long long c, unsigned long long d) {
    unsigned long long s0, s1;
    asm("add.rn.f32x2 %0, %1, %2;" : "=l"(s0) : "l"(a), "l"(b));
    asm("add.rn.f32x2 %0, %1, %2;" : "=l"(s1) : "l"(c), "l"(d));
    asm("add.rn.f32x2 %0, %1, %2;" : "=l"(s0) : "l"(s0), "l"(s1));
    float lo, hi;
    asm("mov.b64 {%0, %1}, %2;" : "=f"(lo), "=f"(hi) : "l"(s0));
    return lo + hi;
}
__device__ __forceinline__ float sigm(float z) {
    return __fdividef(1.0f, 1.0f + __expf(-z));
}

// Full 76-float dot of smem vector (16B-aligned, zero-padded) against 38
// packed-f32x2 register weights. 4 accumulators -> dep chain depth ~10.
__device__ __forceinline__ float dot76(const float* __restrict__ v,
                                       const unsigned long long* __restrict__ w) {
    const ulonglong2* p = (const ulonglong2*)v;
    unsigned long long a0 = 0ull, a1 = 0ull, a2 = 0ull, a3 = 0ull;
#pragma unroll
    for (int i = 0; i < 19; ++i) {
        const ulonglong2 hv = p[i];               // broadcast LDS.128
        if (i & 1) { fma2(a2, w[2 * i], hv.x); fma2(a3, w[2 * i + 1], hv.y); }
        else       { fma2(a0, w[2 * i], hv.x); fma2(a1, w[2 * i + 1], hv.y); }
    }
    return hsum4(a0, a1, a2, a3);
}

// ---------------------------------------------------------------------------
// Kernel 2: persistent-weight recurrence, ONE batch row per block, 256 blocks
// -> 2 independent blocks per SM (mutual latency hiding across barriers).
//   warps 0-2 (75 lanes): A  h_tt     = sigm(W2 . h_{tt-1} + xp_tt + b2)
//   warps 3-5 (75 lanes): B  o_{tt-1} = sigm(Wo . h_{tt-1} + bo)
//   warps 6-9 (128 lanes): C out_{tt-2} = Wfc . o_{tt-2} + bfc
// Each thread owns one full output-row dot (38 packed f32x2 weight regs).
// Double-buffered h/o; ONE __syncthreads per step.
// ---------------------------------------------------------------------------
__global__ __launch_bounds__(NTHR, 2) void rnn_kernel(
    const int*   __restrict__ X,
    const float* __restrict__ W2, const float* __restrict__ b2,
    const float* __restrict__ Wo, const float* __restrict__ bo,
    const float* __restrict__ Wfc, const float* __restrict__ bfc,
    float* __restrict__ out)
{
    __shared__ __align__(16) float hs[2][KP_];   // [buf][k]
    __shared__ __align__(16) float os[2][KP_];
    __shared__ int toks[S_];

    const int tid = threadIdx.x;
    const int wid = tid >> 5;
    const int row = blockIdx.x;                  // one batch row per block

    const bool isA = wid < 3;
    const bool isB = (wid >= 3) && (wid < 6);
    int j      = isA ? tid : (isB ? tid - 96 : tid - 192);
    bool valid = (isA || isB) ? (j < H_) : true;
    if (!valid) j = 0;

    // ---- init state + tokens ----
    for (int i = tid; i < 2 * KP_; i += NTHR) {
        ((float*)hs)[i] = 0.f; ((float*)os)[i] = 0.f;
    }
    for (int i = tid; i < S_; i += NTHR) toks[i] = X[row * S_ + i];

    // ---- weights: one row per thread, packed k-pairs (38 x u64) ----
    const float* wrow = isA ? (W2 + j * H_) : (isB ? (Wo + j * H_) : (Wfc + j * H_));
    unsigned long long w[38];
#pragma unroll
    for (int c = 0; c < 38; ++c) {
        const int k = 2 * c;
        float lo = 0.f, hi = 0.f;
        if (valid) {
            if (k     < H_) lo = wrow[k];
            if (k + 1 < H_) hi = wrow[k + 1];
        }
        w[c] = pack2(lo, hi);
    }
    float br = 0.f;
    if (valid) br = isA ? b2[j] : (isB ? bo[j] : bfc[j]);
    float* outp = out + ((size_t)row * S_) * L_ + j;   // used by C

    __syncthreads();

    float xpv = 0.f;
    if (isA && valid) xpv = g_embp[(size_t)toks[0] * HP_ + j];

    for (int tt = 0; tt < S_ + 2; ++tt) {
        const int pb = tt & 1;
        const bool act = valid &&
            (isA ? (tt < S_) : (isB ? (tt >= 1 && tt <= S_) : (tt >= 2)));

        if (act) {
            if (isA) {
                float xn = 0.f;
                if (tt + 1 < S_)                       // prefetch next xp (overlaps dot)
                    xn = g_embp[(size_t)toks[tt + 1] * HP_ + j];
                const float z = dot76(hs[pb], w) + xpv + br;
                hs[pb ^ 1][j] = sigm(z);               // h_tt
                xpv = xn;
            } else if (isB) {
                const float z = dot76(hs[pb], w) + br;
                os[pb][j] = sigm(z);                   // o_{tt-1}
            } else {
                const float z = dot76(os[pb ^ 1], w) + br;
                outp[(size_t)(tt - 2) * L_] = z;       // out_{tt-2}
            }
        }
        __syncthreads();   // writes target buffers nobody reads this step
    }
}

// ---------------------------------------------------------------------------
extern "C" void kernel_launch(void* const* d_in, const int* in_sizes, int n_in,
                              void* d_out, int out_size) {
    const int*   X   = (const int*)d_in[0];
    const float* emb = (const float*)d_in[1];
    const float* W1  = (const float*)d_in[2];
    const float* b1  = (const float*)d_in[3];
    const float* W2  = (const float*)d_in[4];
    const float* b2  = (const float*)d_in[5];
    const float* Wo  = (const float*)d_in[6];
    const float* bo  = (const float*)d_in[7];
    const float* Wfc = (const float*)d_in[8];
    const float* bfc = (const float*)d_in[9];
    float* out = (float*)d_out;

    embp_kernel<<<V_ / 64, 256>>>(emb, W1, b1);
    rnn_kernel<<<B_, NTHR>>>(X, W2, b2, Wo, bo, Wfc, bfc, out);
}